// round 15
// baseline (speedup 1.0000x reference)
#include <cuda_runtime.h>
#include <cuda_bf16.h>
#include <cstdint>

#define N_NODES 65536
#define C 128
#define BGR 128
#define NPG 512
#define KSEL 256
#define DEG 16
#define E_RAND_PG (NPG * DEG)
#define EPAD 10496
#define MT 768
#define NW 24                      // warps
#define NHW 48                     // half-warps
#define CHUNK 64
#define PADK 136

// ---------------- device scratch ----------------
__device__ __align__(16) float g_h[N_NODES * C];
__device__ __align__(16) float g_xc[N_NODES * C];
__device__ __align__(16) float g_v[C];
__device__ __align__(16) __nv_bfloat16 g_wh[C * C];  // W1^T hi [n][k]
__device__ __align__(16) __nv_bfloat16 g_wl[C * C];  // W1^T lo [n][k]
__device__ float g_c;

__device__ __forceinline__ float wsum(float v) {
    #pragma unroll
    for (int o = 16; o > 0; o >>= 1) v += __shfl_xor_sync(0xffffffffu, v, o);
    return v;
}
__device__ __forceinline__ float wmax(float v) {
    #pragma unroll
    for (int o = 16; o > 0; o >>= 1) v = fmaxf(v, __shfl_xor_sync(0xffffffffu, v, o));
    return v;
}
__device__ __forceinline__ float hsum16(float v) {
    #pragma unroll
    for (int o = 8; o > 0; o >>= 1) v += __shfl_xor_sync(0xffffffffu, v, o);
    return v;
}
__device__ __forceinline__ uint32_t smem_u32(const void* p) {
    uint32_t a;
    asm("{ .reg .u64 t; cvta.to.shared.u64 t, %1; cvt.u32.u64 %0, t; }" : "=r"(a) : "l"(p));
    return a;
}
__device__ __forceinline__ void ldsm4(uint32_t* d, uint32_t addr) {
    asm volatile("ldmatrix.sync.aligned.m8n8.x4.shared.b16 {%0,%1,%2,%3}, [%4];"
                 : "=r"(d[0]), "=r"(d[1]), "=r"(d[2]), "=r"(d[3]) : "r"(addr));
}
__device__ __forceinline__ void mma16816(float* c, const uint32_t* a, const uint32_t* b) {
    asm volatile("mma.sync.aligned.m16n8k16.row.col.f32.bf16.bf16.f32 "
                 "{%0,%1,%2,%3}, {%4,%5,%6,%7}, {%8,%9}, {%0,%1,%2,%3};"
                 : "+f"(c[0]), "+f"(c[1]), "+f"(c[2]), "+f"(c[3])
                 : "r"(a[0]), "r"(a[1]), "r"(a[2]), "r"(a[3]), "r"(b[0]), "r"(b[1]));
}

// ---------------- setup ----------------
__global__ void k_setup(const float* __restrict__ W1,
                        const float* __restrict__ Wp, const float* __restrict__ bp,
                        const float* __restrict__ Wa, const float* __restrict__ ba) {
    int b = blockIdx.x, t = threadIdx.x;
    if (b < C) {
        float w = W1[b * C + t];
        __nv_bfloat16 hi = __float2bfloat16(w);
        g_wh[t * C + b] = hi;
        g_wl[t * C + b] = __float2bfloat16(w - __bfloat162float(hi));
    } else {
        int k = b - C;
        __shared__ float red[4], red2[4];
        int w = t >> 5, lane = t & 31;
        float s = wsum(Wp[k * C + t] * Wa[t]);
        if (lane == 0) red[w] = s;
        if (k == 0) {
            float q = wsum(bp[t] * Wa[t]);
            if (lane == 0) red2[w] = q;
        }
        __syncthreads();
        if (t == 0) {
            g_v[k] = red[0] + red[1] + red[2] + red[3];
            if (k == 0) g_c = red2[0] + red2[1] + red2[2] + red2[3] + ba[0];
        }
    }
}

// ---------------- h = relu(x @ W1 + b1) via mma.sync bf16x3 ----------------
#define TILE_B 34816
#define SM_GEMM (512 + 4 * TILE_B)

__global__ void __launch_bounds__(256)
k_gemm_mma(const float* __restrict__ X, const float* __restrict__ bias) {
    extern __shared__ char smg[];
    float* bias_s = (float*)smg;
    __nv_bfloat16* Ah = (__nv_bfloat16*)(smg + 512);
    __nv_bfloat16* Al = Ah + C * PADK;
    __nv_bfloat16* Bh = Al + C * PADK;
    __nv_bfloat16* Bl = Bh + C * PADK;

    const int tid = threadIdx.x, wid = tid >> 5, lane = tid & 31;
    const int row0 = blockIdx.x * 128;

    if (tid < C) bias_s[tid] = bias[tid];

    #pragma unroll
    for (int i = 0; i < 32; i++) {
        int idx = (i * 256 + tid) * 2;
        int r = idx >> 7, k = idx & 127;
        float2 xv = *(const float2*)&X[(size_t)(row0 + r) * C + k];
        __nv_bfloat16 h0 = __float2bfloat16(xv.x);
        __nv_bfloat16 h1 = __float2bfloat16(xv.y);
        __nv_bfloat16 l0 = __float2bfloat16(xv.x - __bfloat162float(h0));
        __nv_bfloat16 l1 = __float2bfloat16(xv.y - __bfloat162float(h1));
        *(__nv_bfloat162*)&Ah[r * PADK + k] = __nv_bfloat162(h0, h1);
        *(__nv_bfloat162*)&Al[r * PADK + k] = __nv_bfloat162(l0, l1);
        *(uint32_t*)&Bh[r * PADK + k] = *(const uint32_t*)&g_wh[r * C + k];
        *(uint32_t*)&Bl[r * PADK + k] = *(const uint32_t*)&g_wl[r * C + k];
    }
    __syncthreads();

    const uint32_t a_hi = smem_u32(Ah);
    const uint32_t b_hi = smem_u32(Bh);

    float c[16][4];
    #pragma unroll
    for (int nt = 0; nt < 16; nt++)
        #pragma unroll
        for (int q = 0; q < 4; q++) c[nt][q] = 0.f;

    const int wr = wid * 16;
    const int arow = wr + (lane & 7) + ((lane >> 3) & 1) * 8;
    const int brow2 = ((lane >> 4) & 1) * 8 + (lane & 7);
    const int bk_sel = ((lane >> 3) & 1) * 8;

    #pragma unroll
    for (int k0 = 0; k0 < 8; k0++) {
        int akc = k0 * 16 + (lane >> 4) * 8;
        uint32_t aaddr = a_hi + (uint32_t)(arow * PADK + akc) * 2;
        uint32_t ah[4], al[4];
        ldsm4(ah, aaddr);
        ldsm4(al, aaddr + TILE_B);
        #pragma unroll
        for (int nt = 0; nt < 16; nt += 2) {
            uint32_t baddr = b_hi +
                (uint32_t)((nt * 8 + brow2) * PADK + k0 * 16 + bk_sel) * 2;
            uint32_t bh[4], bl[4];
            ldsm4(bh, baddr);
            ldsm4(bl, baddr + TILE_B);
            mma16816(c[nt], ah, bh);
            mma16816(c[nt], ah, bl);
            mma16816(c[nt], al, bh);
            mma16816(c[nt + 1], ah, bh + 2);
            mma16816(c[nt + 1], ah, bl + 2);
            mma16816(c[nt + 1], al, bh + 2);
        }
    }

    const int r = lane >> 2, cq = (lane & 3) * 2;
    #pragma unroll
    for (int nt = 0; nt < 16; nt++) {
        int col = nt * 8 + cq;
        float b0 = bias_s[col], b1 = bias_s[col + 1];
        int row = row0 + wr + r;
        *(float2*)&g_h[(size_t)row * C + col] =
            make_float2(fmaxf(c[nt][0] + b0, 0.f), fmaxf(c[nt][1] + b1, 0.f));
        *(float2*)&g_h[(size_t)(row + 8) * C + col] =
            make_float2(fmaxf(c[nt][2] + b0, 0.f), fmaxf(c[nt][3] + b1, 0.f));
    }
}

// ---------------- mega kernel: one block per graph, 768 threads ----------------
#define SM_BYTES (131072 + 16384 + EPAD * 4 + EPAD * 2 + 2056 + 2048 + 2048)

__device__ __forceinline__ int scan512(int v, int tid, int* scratch) {
    int lane = tid & 31, w = tid >> 5;
    #pragma unroll
    for (int o = 1; o < 32; o <<= 1) {
        int u = __shfl_up_sync(0xffffffffu, v, o);
        if (lane >= o) v += u;
    }
    if (tid < NPG && lane == 31) scratch[w] = v;
    __syncthreads();
    if (tid < 16) {
        int s = scratch[tid];
        #pragma unroll
        for (int o = 1; o < 16; o <<= 1) {
            int u = __shfl_up_sync(0xffffu, s, o);
            if (tid >= o) s += u;
        }
        scratch[tid] = s;
    }
    __syncthreads();
    if (w > 0 && tid < NPG) v += scratch[w - 1];
    return v;
}

extern "C" __global__ void __launch_bounds__(MT, 1)
k_mega(const int* __restrict__ ei, int E,
       const float* __restrict__ Wa,
       const float* __restrict__ Wl1, const float* __restrict__ bl1,
       const float* __restrict__ Wl2,
       const float* __restrict__ Wl3, const float* __restrict__ bl3,
       const float* __restrict__ W2, const float* __restrict__ b2,
       float* __restrict__ out) {
    extern __shared__ char sm[];
    float* tile = (float*)sm;
    float* hdot = tile + NPG * CHUNK;
    float* qd   = hdot + NPG;
    float* smax = qd + NPG;                           // reused as fw[]
    float* sinv = smax + NPG;
    float* f1   = sinv + NPG;
    float* f2   = f1 + NPG;
    float* f3   = f2 + NPG;
    float* fit  = f3 + NPG;
    float* alpha = fit + NPG;                         // [EPAD]
    unsigned short* csr = (unsigned short*)(alpha + EPAD);
    int*   off  = (int*)(csr + EPAD);                 // [NPG+2]
    int*   cur  = off + NPG + 2;                      // [NPG]
    int*   rdeg = cur + NPG;                          // [NPG]

    const int g = blockIdx.x;
    const int base = g * NPG;
    const int tid = threadIdx.x;
    const int wid = tid >> 5;
    const int lane = tid & 31;
    const int hw = tid >> 4;
    const int l16 = tid & 15;
    const int ch4 = l16 * 4;

    // ---- padded local CSR build (pad to multiple of 4) ----
    if (tid < NPG) cur[tid] = 0;
    __syncthreads();
    for (int e = tid; e < E_RAND_PG; e += MT) {
        int dst = ei[(size_t)E + base * DEG + e] - base;
        atomicAdd(&cur[dst], 1);
    }
    __syncthreads();
    int rc = 0, plen = 0;
    if (tid < NPG) {
        rc = cur[tid];
        plen = (rc + 1 + 3) & ~3;
    }
    {
        int v = scan512(plen, tid, (int*)hdot);
        if (tid < NPG) { off[tid + 1] = v; rdeg[tid] = rc + 1; }
        if (tid == 0) off[0] = 0;
    }
    __syncthreads();
    if (tid < NPG) cur[tid] = 0;
    __syncthreads();
    for (int e = tid; e < E_RAND_PG; e += MT) {
        int dst = ei[(size_t)E + base * DEG + e] - base;
        int src = ei[base * DEG + e] - base;
        int p = off[dst] + atomicAdd(&cur[dst], 1);
        csr[p] = (unsigned short)src;
    }
    __syncthreads();
    if (tid < NPG) {
        int p = off[tid] + cur[tid];
        int s1 = off[tid + 1];
        for (; p < s1; p++) csr[p] = (unsigned short)tid;
    }
    __syncthreads();

    const float gc = g_c;
    const float2* t2 = (const float2*)tile;

    // ==== phase A: per-chunk tile load (+hdot), dual-node max sweep ====
    #pragma unroll
    for (int c = 0; c < 2; c++) {
        {
            const float* wa2 = Wa + C + c * CHUNK;
            float w0 = wa2[ch4], w1 = wa2[ch4 + 1], w2 = wa2[ch4 + 2], w3 = wa2[ch4 + 3];
            for (int row = hw; row < NPG; row += NHW) {
                float4 hv = *(const float4*)(g_h + (size_t)(base + row) * C + c * CHUNK + ch4);
                *(float4*)(tile + row * CHUNK + ch4) = hv;
                float p = hsum16(hv.x * w0 + hv.y * w1 + hv.z * w2 + hv.w * w3);
                if (l16 == 0) { if (c == 0) hdot[row] = p; else hdot[row] += p; }
            }
        }
        __syncthreads();
        {
            float vx = g_v[c * CHUNK + lane * 2];
            float vy = g_v[c * CHUNK + lane * 2 + 1];
            for (int n = wid * 2; n < NPG; n += 2 * NW) {
                int s0 = off[n], s1 = off[n + 1], s2 = off[n + 2];
                float mxA = 0.f, myA = 0.f, mxB = 0.f, myB = 0.f;  // h >= 0
                int lenA = s1 - s0, lenB = s2 - s1;
                int iters = ((lenA > lenB ? lenA : lenB)) >> 2;
                for (int t = 0; t < iters; t++) {
                    int eA = s0 + t * 4, eB = s1 + t * 4;
                    bool doA = eA < s1, doB = eB < s2;
                    uint2 ivA, ivB;
                    if (doA) ivA = *(const uint2*)(csr + eA);
                    if (doB) ivB = *(const uint2*)(csr + eB);
                    if (doA) {
                        int i0 = ivA.x & 0xffff, i1 = ivA.x >> 16;
                        int i2 = ivA.y & 0xffff, i3 = ivA.y >> 16;
                        float2 a0 = t2[i0 * 32 + lane], a1 = t2[i1 * 32 + lane];
                        float2 a2 = t2[i2 * 32 + lane], a3 = t2[i3 * 32 + lane];
                        mxA = fmaxf(mxA, fmaxf(fmaxf(a0.x, a1.x), fmaxf(a2.x, a3.x)));
                        myA = fmaxf(myA, fmaxf(fmaxf(a0.y, a1.y), fmaxf(a2.y, a3.y)));
                    }
                    if (doB) {
                        int i0 = ivB.x & 0xffff, i1 = ivB.x >> 16;
                        int i2 = ivB.y & 0xffff, i3 = ivB.y >> 16;
                        float2 a0 = t2[i0 * 32 + lane], a1 = t2[i1 * 32 + lane];
                        float2 a2 = t2[i2 * 32 + lane], a3 = t2[i3 * 32 + lane];
                        mxB = fmaxf(mxB, fmaxf(fmaxf(a0.x, a1.x), fmaxf(a2.x, a3.x)));
                        myB = fmaxf(myB, fmaxf(fmaxf(a0.y, a1.y), fmaxf(a2.y, a3.y)));
                    }
                }
                float pA = wsum(mxA * vx + myA * vy);
                float pB = wsum(mxB * vx + myB * vy);
                if (lane == 0) {
                    if (c == 0) { qd[n] = pA; qd[n + 1] = pB; }
                    else { qd[n] += pA; qd[n + 1] += pB; }
                }
            }
        }
        __syncthreads();
    }

    // ==== phase B: softmax stats over real edges + alpha cache (pad = 0) ====
    for (int n = wid; n < NPG; n += NW) {
        int s0 = off[n];
        int sr = s0 + rdeg[n];
        int s1 = off[n + 1];
        float mh = -3.0e38f;
        for (int e = s0 + lane; e < sr; e += 32) mh = fmaxf(mh, hdot[csr[e]]);
        mh = wmax(mh);
        float q = qd[n] + gc;
        float sm2 = q + mh;
        sm2 = sm2 > 0.f ? sm2 : 0.2f * sm2;
        float ss = 0.f;
        for (int e = s0 + lane; e < sr; e += 32) {
            float sc = q + hdot[csr[e]];
            sc = sc > 0.f ? sc : 0.2f * sc;
            float es = __expf(sc - sm2);
            alpha[e] = es;
            ss += es;
        }
        ss = wsum(ss);
        if (sr + lane < s1) alpha[sr + lane] = 0.f;
        if (lane == 0) sinv[n] = 1.f / ss;
    }
    __syncthreads();

    // ==== phase C: dual-node weighted accumulation ====
    #pragma unroll
    for (int cc = 0; cc < 2; cc++) {
        int c = 1 - cc;  // chunk1 resident first
        if (cc == 1) {
            for (int row = hw; row < NPG; row += NHW) {
                float4 hv = *(const float4*)(g_h + (size_t)(base + row) * C + c * CHUNK + ch4);
                *(float4*)(tile + row * CHUNK + ch4) = hv;
            }
            __syncthreads();
        }
        float w1x = Wl1[c * CHUNK + lane * 2], w1y = Wl1[c * CHUNK + lane * 2 + 1];
        float w2x = Wl2[c * CHUNK + lane * 2], w2y = Wl2[c * CHUNK + lane * 2 + 1];
        float w3x = Wl3[c * CHUNK + lane * 2], w3y = Wl3[c * CHUNK + lane * 2 + 1];
        for (int n = wid * 2; n < NPG; n += 2 * NW) {
            int s0 = off[n], s1 = off[n + 1], s2 = off[n + 2];
            float axA = 0.f, ayA = 0.f, axB = 0.f, ayB = 0.f;
            int lenA = s1 - s0, lenB = s2 - s1;
            int iters = ((lenA > lenB ? lenA : lenB)) >> 2;
            for (int t = 0; t < iters; t++) {
                int eA = s0 + t * 4, eB = s1 + t * 4;
                bool doA = eA < s1, doB = eB < s2;
                uint2 ivA, ivB;
                float4 avA, avB;
                if (doA) { ivA = *(const uint2*)(csr + eA); avA = *(const float4*)(alpha + eA); }
                if (doB) { ivB = *(const uint2*)(csr + eB); avB = *(const float4*)(alpha + eB); }
                if (doA) {
                    int i0 = ivA.x & 0xffff, i1 = ivA.x >> 16;
                    int i2 = ivA.y & 0xffff, i3 = ivA.y >> 16;
                    float2 a0 = t2[i0 * 32 + lane], a1 = t2[i1 * 32 + lane];
                    float2 a2 = t2[i2 * 32 + lane], a3 = t2[i3 * 32 + lane];
                    axA = fmaf(avA.x, a0.x, fmaf(avA.y, a1.x, fmaf(avA.z, a2.x, fmaf(avA.w, a3.x, axA))));
                    ayA = fmaf(avA.x, a0.y, fmaf(avA.y, a1.y, fmaf(avA.z, a2.y, fmaf(avA.w, a3.y, ayA))));
                }
                if (doB) {
                    int i0 = ivB.x & 0xffff, i1 = ivB.x >> 16;
                    int i2 = ivB.y & 0xffff, i3 = ivB.y >> 16;
                    float2 a0 = t2[i0 * 32 + lane], a1 = t2[i1 * 32 + lane];
                    float2 a2 = t2[i2 * 32 + lane], a3 = t2[i3 * 32 + lane];
                    axB = fmaf(avB.x, a0.x, fmaf(avB.y, a1.x, fmaf(avB.z, a2.x, fmaf(avB.w, a3.x, axB))));
                    ayB = fmaf(avB.x, a0.y, fmaf(avB.y, a1.y, fmaf(avB.z, a2.y, fmaf(avB.w, a3.y, ayB))));
                }
            }
            float ivsA = sinv[n], ivsB = sinv[n + 1];
            axA *= ivsA; ayA *= ivsA; axB *= ivsB; ayB *= ivsB;
            *(float2*)(g_xc + (size_t)(base + n) * C + c * CHUNK + lane * 2) =
                make_float2(axA, ayA);
            *(float2*)(g_xc + (size_t)(base + n + 1) * C + c * CHUNK + lane * 2) =
                make_float2(axB, ayB);
            float d1A = wsum(axA * w1x + ayA * w1y);
            float d2A = wsum(axA * w2x + ayA * w2y);
            float d3A = wsum(axA * w3x + ayA * w3y);
            float d1B = wsum(axB * w1x + ayB * w1y);
            float d2B = wsum(axB * w2x + ayB * w2y);
            float d3B = wsum(axB * w3x + ayB * w3y);
            if (lane == 0) {
                if (cc == 0) {
                    f1[n] = d1A; f2[n] = d2A; f3[n] = d3A;
                    f1[n + 1] = d1B; f2[n + 1] = d2B; f3[n + 1] = d3B;
                } else {
                    f1[n] += d1A; f2[n] += d2A; f3[n] += d3A;
                    f1[n + 1] += d1B; f2[n + 1] += d2B; f3[n + 1] += d3B;
                }
            }
        }
        __syncthreads();
    }

    // ==== phase D: LEConv fitness ====
    if (tid < NPG) {
        float deg = (float)rdeg[tid];
        f1[tid] = f1[tid] + bl1[0];
        f3[tid] = f3[tid] + bl3[0] - deg * f2[tid];
    }
    __syncthreads();
    for (int n = wid; n < NPG; n += NW) {
        int s0 = off[n];
        int sr = s0 + rdeg[n];
        float s = 0.f;
        for (int e = s0 + lane; e < sr; e += 32) s += f1[csr[e]];
        s = wsum(s);
        if (lane == 0) fit[n] = 1.f / (1.f + __expf(-(f3[n] + s)));
    }
    __syncthreads();

    // ==== phase E: rank-based top-K (desc, tie -> smaller index) ====
    int* sidx = cur;
    float* fw = smax;
    int selv = 0;
    float fi = 0.f;
    if (tid < NPG) {
        fi = fit[tid];
        int r = 0;
        for (int j = 0; j < NPG; j++) {
            float fj = fit[j];
            r += (fj > fi || (fj == fi && j < tid)) ? 1 : 0;
        }
        selv = (r < KSEL) ? 1 : 0;
    }
    int pos = scan512(selv, tid, (int*)hdot);
    __syncthreads();
    if (tid < NPG && selv) { sidx[pos - 1] = tid; fw[pos - 1] = fi; }
    __syncthreads();

    // ==== phase F: S = sum_sel fit*xc ; out = (S/K)@W2 + b2 ====
    {
        int ch = tid & 127, grp = tid >> 7;  // 6 groups
        float acc = 0.f;
        for (int r = grp; r < KSEL; r += MT / 128) {
            int node = sidx[r];
            acc = fmaf(fw[r], g_xc[(size_t)(base + node) * C + ch], acc);
        }
        tile[tid] = acc;
    }
    __syncthreads();
    if (tid < C) {
        float s = 0.f;
        #pragma unroll
        for (int k2 = 0; k2 < MT / 128; k2++) s += tile[tid + 128 * k2];
        qd[tid] = s * (1.f / (float)KSEL);
    }
    __syncthreads();
    if (tid < C) {
        float acc = b2[tid];
        #pragma unroll 4
        for (int c = 0; c < C; c++) acc = fmaf(qd[c], W2[c * C + tid], acc);
        out[g * C + tid] = acc;
    }
}

// ---------------- launcher ----------------
extern "C" void kernel_launch(void* const* d_in, const int* in_sizes, int n_in,
                              void* d_out, int out_size) {
    const float* x   = (const float*)d_in[0];
    const float* W1  = (const float*)d_in[1];
    const float* b1  = (const float*)d_in[2];
    const float* Wp  = (const float*)d_in[3];
    const float* bp  = (const float*)d_in[4];
    const float* Wa  = (const float*)d_in[5];
    const float* ba  = (const float*)d_in[6];
    const float* Wl1 = (const float*)d_in[7];
    const float* bl1 = (const float*)d_in[8];
    const float* Wl2 = (const float*)d_in[9];
    const float* Wl3 = (const float*)d_in[10];
    const float* bl3 = (const float*)d_in[11];
    const float* W2  = (const float*)d_in[12];
    const float* b2  = (const float*)d_in[13];
    const int*   ei  = (const int*)d_in[14];
    int E = in_sizes[14] / 2;
    float* out = (float*)d_out;

    cudaFuncSetAttribute(k_gemm_mma, cudaFuncAttributeMaxDynamicSharedMemorySize, SM_GEMM);
    cudaFuncSetAttribute(k_mega, cudaFuncAttributeMaxDynamicSharedMemorySize, SM_BYTES);

    k_setup<<<2 * C, 128>>>(W1, Wp, bp, Wa, ba);
    k_gemm_mma<<<N_NODES / 128, 256, SM_GEMM>>>(x, b1);
    k_mega<<<BGR, MT, SM_BYTES>>>(ei, E, Wa, Wl1, bl1, Wl2, Wl3, bl3,
                                  W2, b2, out);
}

// round 16
// speedup vs baseline: 1.0991x; 1.0991x over previous
#include <cuda_runtime.h>
#include <cuda_bf16.h>
#include <cstdint>

#define N_NODES 65536
#define C 128
#define BGR 128
#define NPG 512
#define KSEL 256
#define DEG 16
#define E_RAND_PG (NPG * DEG)
#define EPAD 10496
#define MT 1024
#define EPT 8                      // edges per thread (8192/1024)
#define CHUNK 64
#define PADK 136

// ---------------- device scratch ----------------
__device__ __align__(16) float g_h[N_NODES * C];
__device__ __align__(16) float g_xc[N_NODES * C];
__device__ __align__(16) float g_v[C];
__device__ __align__(16) __nv_bfloat16 g_wh[C * C];  // W1^T hi [n][k]
__device__ __align__(16) __nv_bfloat16 g_wl[C * C];  // W1^T lo [n][k]
__device__ float g_c;

__device__ __forceinline__ float wsum(float v) {
    #pragma unroll
    for (int o = 16; o > 0; o >>= 1) v += __shfl_xor_sync(0xffffffffu, v, o);
    return v;
}
__device__ __forceinline__ float wmax(float v) {
    #pragma unroll
    for (int o = 16; o > 0; o >>= 1) v = fmaxf(v, __shfl_xor_sync(0xffffffffu, v, o));
    return v;
}
__device__ __forceinline__ float hsum16(float v) {
    #pragma unroll
    for (int o = 8; o > 0; o >>= 1) v += __shfl_xor_sync(0xffffffffu, v, o);
    return v;
}
__device__ __forceinline__ uint32_t smem_u32(const void* p) {
    uint32_t a;
    asm("{ .reg .u64 t; cvta.to.shared.u64 t, %1; cvt.u32.u64 %0, t; }" : "=r"(a) : "l"(p));
    return a;
}
__device__ __forceinline__ void ldsm4(uint32_t* d, uint32_t addr) {
    asm volatile("ldmatrix.sync.aligned.m8n8.x4.shared.b16 {%0,%1,%2,%3}, [%4];"
                 : "=r"(d[0]), "=r"(d[1]), "=r"(d[2]), "=r"(d[3]) : "r"(addr));
}
__device__ __forceinline__ void mma16816(float* c, const uint32_t* a, const uint32_t* b) {
    asm volatile("mma.sync.aligned.m16n8k16.row.col.f32.bf16.bf16.f32 "
                 "{%0,%1,%2,%3}, {%4,%5,%6,%7}, {%8,%9}, {%0,%1,%2,%3};"
                 : "+f"(c[0]), "+f"(c[1]), "+f"(c[2]), "+f"(c[3])
                 : "r"(a[0]), "r"(a[1]), "r"(a[2]), "r"(a[3]), "r"(b[0]), "r"(b[1]));
}

// ---------------- setup ----------------
__global__ void k_setup(const float* __restrict__ W1,
                        const float* __restrict__ Wp, const float* __restrict__ bp,
                        const float* __restrict__ Wa, const float* __restrict__ ba) {
    int b = blockIdx.x, t = threadIdx.x;
    if (b < C) {
        float w = W1[b * C + t];
        __nv_bfloat16 hi = __float2bfloat16(w);
        g_wh[t * C + b] = hi;
        g_wl[t * C + b] = __float2bfloat16(w - __bfloat162float(hi));
    } else {
        int k = b - C;
        __shared__ float red[4], red2[4];
        int w = t >> 5, lane = t & 31;
        float s = wsum(Wp[k * C + t] * Wa[t]);
        if (lane == 0) red[w] = s;
        if (k == 0) {
            float q = wsum(bp[t] * Wa[t]);
            if (lane == 0) red2[w] = q;
        }
        __syncthreads();
        if (t == 0) {
            g_v[k] = red[0] + red[1] + red[2] + red[3];
            if (k == 0) g_c = red2[0] + red2[1] + red2[2] + red2[3] + ba[0];
        }
    }
}

// ---------------- h = relu(x @ W1 + b1) via mma.sync bf16x3 ----------------
#define TILE_B 34816
#define SM_GEMM (512 + 4 * TILE_B)

__global__ void __launch_bounds__(256)
k_gemm_mma(const float* __restrict__ X, const float* __restrict__ bias) {
    extern __shared__ char smg[];
    float* bias_s = (float*)smg;
    __nv_bfloat16* Ah = (__nv_bfloat16*)(smg + 512);
    __nv_bfloat16* Al = Ah + C * PADK;
    __nv_bfloat16* Bh = Al + C * PADK;
    __nv_bfloat16* Bl = Bh + C * PADK;

    const int tid = threadIdx.x, wid = tid >> 5, lane = tid & 31;
    const int row0 = blockIdx.x * 128;

    if (tid < C) bias_s[tid] = bias[tid];

    #pragma unroll
    for (int i = 0; i < 32; i++) {
        int idx = (i * 256 + tid) * 2;
        int r = idx >> 7, k = idx & 127;
        float2 xv = *(const float2*)&X[(size_t)(row0 + r) * C + k];
        __nv_bfloat16 h0 = __float2bfloat16(xv.x);
        __nv_bfloat16 h1 = __float2bfloat16(xv.y);
        __nv_bfloat16 l0 = __float2bfloat16(xv.x - __bfloat162float(h0));
        __nv_bfloat16 l1 = __float2bfloat16(xv.y - __bfloat162float(h1));
        *(__nv_bfloat162*)&Ah[r * PADK + k] = __nv_bfloat162(h0, h1);
        *(__nv_bfloat162*)&Al[r * PADK + k] = __nv_bfloat162(l0, l1);
        *(uint32_t*)&Bh[r * PADK + k] = *(const uint32_t*)&g_wh[r * C + k];
        *(uint32_t*)&Bl[r * PADK + k] = *(const uint32_t*)&g_wl[r * C + k];
    }
    __syncthreads();

    const uint32_t a_hi = smem_u32(Ah);
    const uint32_t b_hi = smem_u32(Bh);

    float c[16][4];
    #pragma unroll
    for (int nt = 0; nt < 16; nt++)
        #pragma unroll
        for (int q = 0; q < 4; q++) c[nt][q] = 0.f;

    const int wr = wid * 16;
    const int arow = wr + (lane & 7) + ((lane >> 3) & 1) * 8;
    const int brow2 = ((lane >> 4) & 1) * 8 + (lane & 7);
    const int bk_sel = ((lane >> 3) & 1) * 8;

    #pragma unroll
    for (int k0 = 0; k0 < 8; k0++) {
        int akc = k0 * 16 + (lane >> 4) * 8;
        uint32_t aaddr = a_hi + (uint32_t)(arow * PADK + akc) * 2;
        uint32_t ah[4], al[4];
        ldsm4(ah, aaddr);
        ldsm4(al, aaddr + TILE_B);
        #pragma unroll
        for (int nt = 0; nt < 16; nt += 2) {
            uint32_t baddr = b_hi +
                (uint32_t)((nt * 8 + brow2) * PADK + k0 * 16 + bk_sel) * 2;
            uint32_t bh[4], bl[4];
            ldsm4(bh, baddr);
            ldsm4(bl, baddr + TILE_B);
            mma16816(c[nt], ah, bh);
            mma16816(c[nt], ah, bl);
            mma16816(c[nt], al, bh);
            mma16816(c[nt + 1], ah, bh + 2);
            mma16816(c[nt + 1], ah, bl + 2);
            mma16816(c[nt + 1], al, bh + 2);
        }
    }

    const int r = lane >> 2, cq = (lane & 3) * 2;
    #pragma unroll
    for (int nt = 0; nt < 16; nt++) {
        int col = nt * 8 + cq;
        float b0 = bias_s[col], b1 = bias_s[col + 1];
        int row = row0 + wr + r;
        *(float2*)&g_h[(size_t)row * C + col] =
            make_float2(fmaxf(c[nt][0] + b0, 0.f), fmaxf(c[nt][1] + b1, 0.f));
        *(float2*)&g_h[(size_t)(row + 8) * C + col] =
            make_float2(fmaxf(c[nt][2] + b0, 0.f), fmaxf(c[nt][3] + b1, 0.f));
    }
}

// ---------------- mega kernel: one block per graph, 1024 threads ----------------
#define SM_BYTES (131072 + 16384 + EPAD * 4 + EPAD * 2 + 2056 + 2048 + 2048)

__device__ __forceinline__ int scan512(int v, int tid, int* scratch) {
    int lane = tid & 31, w = tid >> 5;
    #pragma unroll
    for (int o = 1; o < 32; o <<= 1) {
        int u = __shfl_up_sync(0xffffffffu, v, o);
        if (lane >= o) v += u;
    }
    if (tid < NPG && lane == 31) scratch[w] = v;
    __syncthreads();
    if (tid < 16) {
        int s = scratch[tid];
        #pragma unroll
        for (int o = 1; o < 16; o <<= 1) {
            int u = __shfl_up_sync(0xffffu, s, o);
            if (tid >= o) s += u;
        }
        scratch[tid] = s;
    }
    __syncthreads();
    if (w > 0 && tid < NPG) v += scratch[w - 1];
    return v;
}

extern "C" __global__ void __launch_bounds__(MT, 1)
k_mega(const int* __restrict__ ei, int E,
       const float* __restrict__ Wa,
       const float* __restrict__ Wl1, const float* __restrict__ bl1,
       const float* __restrict__ Wl2,
       const float* __restrict__ Wl3, const float* __restrict__ bl3,
       const float* __restrict__ W2, const float* __restrict__ b2,
       float* __restrict__ out) {
    extern __shared__ char sm[];
    float* tile = (float*)sm;
    float* hdot = tile + NPG * CHUNK;
    float* qd   = hdot + NPG;
    float* smax = qd + NPG;                           // reused as fw[]
    float* sinv = smax + NPG;
    float* f1   = sinv + NPG;
    float* f2   = f1 + NPG;
    float* f3   = f2 + NPG;
    float* fit  = f3 + NPG;
    float* alpha = fit + NPG;                         // [EPAD]
    unsigned short* csr = (unsigned short*)(alpha + EPAD);
    int*   off  = (int*)(csr + EPAD);                 // [NPG+2]
    int*   cur  = off + NPG + 2;                      // [NPG]
    int*   rdeg = cur + NPG;                          // [NPG]

    const int g = blockIdx.x;
    const int base = g * NPG;
    const int tid = threadIdx.x;
    const int wid = tid >> 5;
    const int lane = tid & 31;
    const int hw = tid >> 4;
    const int l16 = tid & 15;
    const int ch4 = l16 * 4;

    // ---- padded local CSR build: ONE atomic pass ----
    if (tid < NPG) cur[tid] = 0;
    __syncthreads();
    int mdst[EPT], msrc[EPT], mpos[EPT];
    #pragma unroll
    for (int i = 0; i < EPT; i++) {
        int e = tid + i * MT;
        mdst[i] = ei[(size_t)E + base * DEG + e] - base;
        msrc[i] = ei[base * DEG + e] - base;
        mpos[i] = atomicAdd(&cur[mdst[i]], 1);
    }
    __syncthreads();
    int rc = 0, plen = 0;
    if (tid < NPG) {
        rc = cur[tid];
        plen = (rc + 1 + 3) & ~3;
    }
    {
        int v = scan512(plen, tid, (int*)hdot);
        if (tid < NPG) { off[tid + 1] = v; rdeg[tid] = rc + 1; }
        if (tid == 0) off[0] = 0;
    }
    __syncthreads();
    #pragma unroll
    for (int i = 0; i < EPT; i++)
        csr[off[mdst[i]] + mpos[i]] = (unsigned short)msrc[i];
    __syncthreads();
    if (tid < NPG) {
        int p = off[tid] + rc;              // self + pad with self (exact for max)
        int s1 = off[tid + 1];
        for (; p < s1; p++) csr[p] = (unsigned short)tid;
    }
    __syncthreads();

    const float gc = g_c;
    const float2* t2 = (const float2*)tile;

    // ==== phase A: per-chunk tile load (+hdot), dual-node max sweep ====
    #pragma unroll
    for (int c = 0; c < 2; c++) {
        {
            const float* wa2 = Wa + C + c * CHUNK;
            float w0 = wa2[ch4], w1 = wa2[ch4 + 1], w2 = wa2[ch4 + 2], w3 = wa2[ch4 + 3];
            #pragma unroll
            for (int r = 0; r < 8; r++) {
                int row = hw + r * 64;
                float4 hv = *(const float4*)(g_h + (size_t)(base + row) * C + c * CHUNK + ch4);
                *(float4*)(tile + row * CHUNK + ch4) = hv;
                float p = hsum16(hv.x * w0 + hv.y * w1 + hv.z * w2 + hv.w * w3);
                if (l16 == 0) { if (c == 0) hdot[row] = p; else hdot[row] += p; }
            }
        }
        __syncthreads();
        {
            float vx = g_v[c * CHUNK + lane * 2];
            float vy = g_v[c * CHUNK + lane * 2 + 1];
            for (int n = wid * 2; n < NPG; n += 64) {
                int s0 = off[n], s1 = off[n + 1], s2 = off[n + 2];
                float mxA = 0.f, myA = 0.f, mxB = 0.f, myB = 0.f;  // h >= 0
                int lenA = s1 - s0, lenB = s2 - s1;
                int iters = ((lenA > lenB ? lenA : lenB)) >> 2;
                for (int t = 0; t < iters; t++) {
                    int eA = s0 + t * 4, eB = s1 + t * 4;
                    if (eA < s1) {
                        uint2 iv = *(const uint2*)(csr + eA);
                        int i0 = iv.x & 0xffff, i1 = iv.x >> 16;
                        int i2 = iv.y & 0xffff, i3 = iv.y >> 16;
                        float2 a0 = t2[i0 * 32 + lane], a1 = t2[i1 * 32 + lane];
                        float2 a2 = t2[i2 * 32 + lane], a3 = t2[i3 * 32 + lane];
                        mxA = fmaxf(mxA, fmaxf(fmaxf(a0.x, a1.x), fmaxf(a2.x, a3.x)));
                        myA = fmaxf(myA, fmaxf(fmaxf(a0.y, a1.y), fmaxf(a2.y, a3.y)));
                    }
                    if (eB < s2) {
                        uint2 iv = *(const uint2*)(csr + eB);
                        int i0 = iv.x & 0xffff, i1 = iv.x >> 16;
                        int i2 = iv.y & 0xffff, i3 = iv.y >> 16;
                        float2 a0 = t2[i0 * 32 + lane], a1 = t2[i1 * 32 + lane];
                        float2 a2 = t2[i2 * 32 + lane], a3 = t2[i3 * 32 + lane];
                        mxB = fmaxf(mxB, fmaxf(fmaxf(a0.x, a1.x), fmaxf(a2.x, a3.x)));
                        myB = fmaxf(myB, fmaxf(fmaxf(a0.y, a1.y), fmaxf(a2.y, a3.y)));
                    }
                }
                float pA = wsum(mxA * vx + myA * vy);
                float pB = wsum(mxB * vx + myB * vy);
                if (lane == 0) {
                    if (c == 0) { qd[n] = pA; qd[n + 1] = pB; }
                    else { qd[n] += pA; qd[n + 1] += pB; }
                }
            }
        }
        __syncthreads();
    }

    // ==== phase B: softmax stats over real edges + alpha cache (pad = 0) ====
    for (int n = wid; n < NPG; n += 32) {
        int s0 = off[n];
        int sr = s0 + rdeg[n];
        int s1 = off[n + 1];
        float mh = -3.0e38f;
        for (int e = s0 + lane; e < sr; e += 32) mh = fmaxf(mh, hdot[csr[e]]);
        mh = wmax(mh);
        float q = qd[n] + gc;
        float sm2 = q + mh;
        sm2 = sm2 > 0.f ? sm2 : 0.2f * sm2;
        float ss = 0.f;
        for (int e = s0 + lane; e < sr; e += 32) {
            float sc = q + hdot[csr[e]];
            sc = sc > 0.f ? sc : 0.2f * sc;
            float es = __expf(sc - sm2);
            alpha[e] = es;
            ss += es;
        }
        ss = wsum(ss);
        if (sr + lane < s1) alpha[sr + lane] = 0.f;
        if (lane == 0) sinv[n] = 1.f / ss;
    }
    __syncthreads();

    // ==== phase C: dual-node weighted accumulation ====
    #pragma unroll
    for (int cc = 0; cc < 2; cc++) {
        int c = 1 - cc;  // chunk1 resident first
        if (cc == 1) {
            #pragma unroll
            for (int r = 0; r < 8; r++) {
                int row = hw + r * 64;
                float4 hv = *(const float4*)(g_h + (size_t)(base + row) * C + c * CHUNK + ch4);
                *(float4*)(tile + row * CHUNK + ch4) = hv;
            }
            __syncthreads();
        }
        float w1x = Wl1[c * CHUNK + lane * 2], w1y = Wl1[c * CHUNK + lane * 2 + 1];
        float w2x = Wl2[c * CHUNK + lane * 2], w2y = Wl2[c * CHUNK + lane * 2 + 1];
        float w3x = Wl3[c * CHUNK + lane * 2], w3y = Wl3[c * CHUNK + lane * 2 + 1];
        for (int n = wid * 2; n < NPG; n += 64) {
            int s0 = off[n], s1 = off[n + 1], s2 = off[n + 2];
            float axA = 0.f, ayA = 0.f, axB = 0.f, ayB = 0.f;
            int lenA = s1 - s0, lenB = s2 - s1;
            int iters = ((lenA > lenB ? lenA : lenB)) >> 2;
            for (int t = 0; t < iters; t++) {
                int eA = s0 + t * 4, eB = s1 + t * 4;
                if (eA < s1) {
                    uint2 iv = *(const uint2*)(csr + eA);
                    float4 av = *(const float4*)(alpha + eA);
                    int i0 = iv.x & 0xffff, i1 = iv.x >> 16;
                    int i2 = iv.y & 0xffff, i3 = iv.y >> 16;
                    float2 a0 = t2[i0 * 32 + lane], a1 = t2[i1 * 32 + lane];
                    float2 a2 = t2[i2 * 32 + lane], a3 = t2[i3 * 32 + lane];
                    axA = fmaf(av.x, a0.x, fmaf(av.y, a1.x, fmaf(av.z, a2.x, fmaf(av.w, a3.x, axA))));
                    ayA = fmaf(av.x, a0.y, fmaf(av.y, a1.y, fmaf(av.z, a2.y, fmaf(av.w, a3.y, ayA))));
                }
                if (eB < s2) {
                    uint2 iv = *(const uint2*)(csr + eB);
                    float4 av = *(const float4*)(alpha + eB);
                    int i0 = iv.x & 0xffff, i1 = iv.x >> 16;
                    int i2 = iv.y & 0xffff, i3 = iv.y >> 16;
                    float2 a0 = t2[i0 * 32 + lane], a1 = t2[i1 * 32 + lane];
                    float2 a2 = t2[i2 * 32 + lane], a3 = t2[i3 * 32 + lane];
                    axB = fmaf(av.x, a0.x, fmaf(av.y, a1.x, fmaf(av.z, a2.x, fmaf(av.w, a3.x, axB))));
                    ayB = fmaf(av.x, a0.y, fmaf(av.y, a1.y, fmaf(av.z, a2.y, fmaf(av.w, a3.y, ayB))));
                }
            }
            float ivA = sinv[n], ivB = sinv[n + 1];
            axA *= ivA; ayA *= ivA; axB *= ivB; ayB *= ivB;
            *(float2*)(g_xc + (size_t)(base + n) * C + c * CHUNK + lane * 2) =
                make_float2(axA, ayA);
            *(float2*)(g_xc + (size_t)(base + n + 1) * C + c * CHUNK + lane * 2) =
                make_float2(axB, ayB);
            float d1A = wsum(axA * w1x + ayA * w1y);
            float d2A = wsum(axA * w2x + ayA * w2y);
            float d3A = wsum(axA * w3x + ayA * w3y);
            float d1B = wsum(axB * w1x + ayB * w1y);
            float d2B = wsum(axB * w2x + ayB * w2y);
            float d3B = wsum(axB * w3x + ayB * w3y);
            if (lane == 0) {
                if (cc == 0) {
                    f1[n] = d1A; f2[n] = d2A; f3[n] = d3A;
                    f1[n + 1] = d1B; f2[n + 1] = d2B; f3[n + 1] = d3B;
                } else {
                    f1[n] += d1A; f2[n] += d2A; f3[n] += d3A;
                    f1[n + 1] += d1B; f2[n + 1] += d2B; f3[n + 1] += d3B;
                }
            }
        }
        __syncthreads();
    }

    // ==== phase D: LEConv fitness ====
    if (tid < NPG) {
        float deg = (float)rdeg[tid];
        f1[tid] = f1[tid] + bl1[0];
        f3[tid] = f3[tid] + bl3[0] - deg * f2[tid];
    }
    __syncthreads();
    for (int n = wid; n < NPG; n += 32) {
        int s0 = off[n];
        int sr = s0 + rdeg[n];
        float s = 0.f;
        for (int e = s0 + lane; e < sr; e += 32) s += f1[csr[e]];
        s = wsum(s);
        if (lane == 0) fit[n] = 1.f / (1.f + __expf(-(f3[n] + s)));
    }
    __syncthreads();

    // ==== phase E: rank-based top-K (desc, tie -> smaller index) ====
    int* sidx = cur;
    float* fw = smax;
    int selv = 0;
    float fi = 0.f;
    if (tid < NPG) {
        fi = fit[tid];
        int r = 0;
        for (int j = 0; j < NPG; j++) {
            float fj = fit[j];
            r += (fj > fi || (fj == fi && j < tid)) ? 1 : 0;
        }
        selv = (r < KSEL) ? 1 : 0;
    }
    int pos = scan512(selv, tid, (int*)hdot);
    __syncthreads();
    if (tid < NPG && selv) { sidx[pos - 1] = tid; fw[pos - 1] = fi; }
    __syncthreads();

    // ==== phase F ====
    {
        int ch = tid & 127, grp = tid >> 7;
        float acc = 0.f;
        for (int r = grp * 32; r < grp * 32 + 32; r++) {
            int node = sidx[r];
            acc = fmaf(fw[r], g_xc[(size_t)(base + node) * C + ch], acc);
        }
        tile[tid] = acc;
    }
    __syncthreads();
    if (tid < C) {
        float s = 0.f;
        #pragma unroll
        for (int k2 = 0; k2 < 8; k2++) s += tile[tid + 128 * k2];
        qd[tid] = s * (1.f / (float)KSEL);
    }
    __syncthreads();
    if (tid < C) {
        float acc = b2[tid];
        #pragma unroll 4
        for (int c = 0; c < C; c++) acc = fmaf(qd[c], W2[c * C + tid], acc);
        out[g * C + tid] = acc;
    }
}

// ---------------- launcher ----------------
extern "C" void kernel_launch(void* const* d_in, const int* in_sizes, int n_in,
                              void* d_out, int out_size) {
    const float* x   = (const float*)d_in[0];
    const float* W1  = (const float*)d_in[1];
    const float* b1  = (const float*)d_in[2];
    const float* Wp  = (const float*)d_in[3];
    const float* bp  = (const float*)d_in[4];
    const float* Wa  = (const float*)d_in[5];
    const float* ba  = (const float*)d_in[6];
    const float* Wl1 = (const float*)d_in[7];
    const float* bl1 = (const float*)d_in[8];
    const float* Wl2 = (const float*)d_in[9];
    const float* Wl3 = (const float*)d_in[10];
    const float* bl3 = (const float*)d_in[11];
    const float* W2  = (const float*)d_in[12];
    const float* b2  = (const float*)d_in[13];
    const int*   ei  = (const int*)d_in[14];
    int E = in_sizes[14] / 2;
    float* out = (float*)d_out;

    cudaFuncSetAttribute(k_gemm_mma, cudaFuncAttributeMaxDynamicSharedMemorySize, SM_GEMM);
    cudaFuncSetAttribute(k_mega, cudaFuncAttributeMaxDynamicSharedMemorySize, SM_BYTES);

    k_setup<<<2 * C, 128>>>(W1, Wp, bp, Wa, ba);
    k_gemm_mma<<<N_NODES / 128, 256, SM_GEMM>>>(x, b1);
    k_mega<<<BGR, MT, SM_BYTES>>>(ei, E, Wa, Wl1, bl1, Wl2, Wl3, bl3,
                                  W2, b2, out);
}